// round 2
// baseline (speedup 1.0000x reference)
#include <cuda_runtime.h>
#include <math.h>

// Problem constants
#define E   4096
#define BB  8          // batch
#define TJ  512        // columns per block in K1 (128 threads * float4)
#define TK  32         // rows per split in K1 (halved vs R1 -> 2x grid)
#define NSPLIT (E / TK)   // 128 row-splits
#define NCOLB  (E / TJ)   // 8 column blocks

// Deterministic split-K scratch: [NSPLIT][BB][E] fp32 = 16 MB
__device__ float g_scratch[(size_t)NSPLIT * BB * E];

// ---------------------------------------------------------------------------
// K1: stream w/alpha/hebb once (192 MB). Each block: 32 rows x 512 cols.
// acc[b][c] += yin[b,k] * (w[k,j] + alpha[k,j]*hebb[k,j])
// Partials written to g_scratch[split][b][j]  (no atomics -> deterministic).
// ---------------------------------------------------------------------------
__global__ __launch_bounds__(128)
void k1_partial_gemm(const float* __restrict__ yin,
                     const float* __restrict__ hebb,
                     const float* __restrict__ w,
                     const float* __restrict__ alpha)
{
    const int cb  = blockIdx.x;            // 0..NCOLB-1
    const int rb  = blockIdx.y;            // 0..NSPLIT-1
    const int tid = threadIdx.x;           // 0..127
    const int j0  = cb * TJ + tid * 4;     // this thread's 4 columns
    const int k0  = rb * TK;

    // Stage yin[b, k0:k0+TK] in smem (broadcast reuse across 128 threads)
    __shared__ float yin_s[BB][TK];
    for (int i = tid; i < BB * TK; i += 128) {
        int b = i / TK, k = i % TK;
        yin_s[b][k] = yin[(size_t)b * E + k0 + k];
    }
    __syncthreads();

    float acc[BB][4];
#pragma unroll
    for (int b = 0; b < BB; b++) {
        acc[b][0] = 0.f; acc[b][1] = 0.f; acc[b][2] = 0.f; acc[b][3] = 0.f;
    }

#pragma unroll 8
    for (int k = 0; k < TK; k++) {
        const size_t base = (size_t)(k0 + k) * E + j0;
        const float4 w4 = *(const float4*)(w     + base);
        const float4 a4 = *(const float4*)(alpha + base);
        const float4 h4 = *(const float4*)(hebb  + base);
        float4 m;
        m.x = fmaf(a4.x, h4.x, w4.x);
        m.y = fmaf(a4.y, h4.y, w4.y);
        m.z = fmaf(a4.z, h4.z, w4.z);
        m.w = fmaf(a4.w, h4.w, w4.w);
#pragma unroll
        for (int b = 0; b < BB; b++) {
            const float yv = yin_s[b][k];
            acc[b][0] = fmaf(yv, m.x, acc[b][0]);
            acc[b][1] = fmaf(yv, m.y, acc[b][1]);
            acc[b][2] = fmaf(yv, m.z, acc[b][2]);
            acc[b][3] = fmaf(yv, m.w, acc[b][3]);
        }
    }

#pragma unroll
    for (int b = 0; b < BB; b++) {
        float4 v = make_float4(acc[b][0], acc[b][1], acc[b][2], acc[b][3]);
        *(float4*)(g_scratch + ((size_t)rb * BB + b) * E + j0) = v;
    }
}

// ---------------------------------------------------------------------------
// K2: reduce splits + input, tanh -> yout (written to d_out[0 : BB*E])
// ---------------------------------------------------------------------------
__global__ __launch_bounds__(256)
void k2_yout(const float* __restrict__ input, float* __restrict__ yout)
{
    const int idx = blockIdx.x * 256 + threadIdx.x;  // 0 .. BB*E-1
    if (idx >= BB * E) return;
    float s = input[idx];
#pragma unroll
    for (int r = 0; r < NSPLIT; r++)
        s += g_scratch[(size_t)r * BB * E + idx];
    yout[idx] = tanhf(s);
}

// ---------------------------------------------------------------------------
// K3: hebb_new = (1-eta)*hebb + eta * yin0 (outer) yout0   (128 MB stream)
// ---------------------------------------------------------------------------
__global__ __launch_bounds__(256)
void k3_hebb(const float* __restrict__ hebb,
             const float* __restrict__ yin,    // row 0 used
             const float* __restrict__ eta,    // scalar
             const float* __restrict__ yout0,  // d_out row 0 (E floats)
             float* __restrict__ hebb_out)
{
    const float et    = eta[0];
    const float one_m = 1.0f - et;

    const int t = blockIdx.x * 256 + threadIdx.x;     // one float4 per thread
    const int n4 = (E * E) / 4;
    if (t >= n4) return;

    const int row = t / (E / 4);
    const int c4  = t % (E / 4);
    const float s = et * yin[row];                    // eta * yin0[row]

    const float4 h = *(const float4*)(hebb  + (size_t)t * 4);
    const float4 y = *(const float4*)(yout0 + (size_t)c4 * 4);
    float4 o;
    o.x = fmaf(one_m, h.x, s * y.x);
    o.y = fmaf(one_m, h.y, s * y.y);
    o.z = fmaf(one_m, h.z, s * y.z);
    o.w = fmaf(one_m, h.w, s * y.w);
    *(float4*)(hebb_out + (size_t)t * 4) = o;
}

// ---------------------------------------------------------------------------
// Launch: inputs in metadata order: input, yin, hebb, w, alpha, eta
// Output: [yout (8*4096) | hebb_new (4096*4096)] fp32
// ---------------------------------------------------------------------------
extern "C" void kernel_launch(void* const* d_in, const int* in_sizes, int n_in,
                              void* d_out, int out_size)
{
    const float* input = (const float*)d_in[0];
    const float* yin   = (const float*)d_in[1];
    const float* hebb  = (const float*)d_in[2];
    const float* w     = (const float*)d_in[3];
    const float* alpha = (const float*)d_in[4];
    const float* eta   = (const float*)d_in[5];

    float* out      = (float*)d_out;
    float* yout     = out;            // BB*E
    float* hebb_out = out + BB * E;   // E*E

    // K1: 8 col-blocks x 128 row-splits = 1024 blocks
    dim3 g1(NCOLB, NSPLIT);
    k1_partial_gemm<<<g1, 128>>>(yin, hebb, w, alpha);

    // K2: 32768 elems
    k2_yout<<<(BB * E + 255) / 256, 256>>>(input, yout);

    // K3: E*E/4 float4 threads
    const int n4 = (E * E) / 4;
    k3_hebb<<<(n4 + 255) / 256, 256>>>(hebb, yin, eta, yout, hebb_out);
}

// round 3
// speedup vs baseline: 1.0641x; 1.0641x over previous
#include <cuda_runtime.h>
#include <math.h>

// Problem constants
#define E   4096
#define BB  8          // batch
#define TJ  512        // columns per block in K1 (128 threads * float4)
#define TK  64         // rows per split in K1
#define NSPLIT (E / TK)   // 64 row-splits
#define NCOLB  (E / TJ)   // 8 column blocks

// Deterministic split-K scratch: [NSPLIT][BB][E] fp32 = 8 MB
__device__ float g_scratch[(size_t)NSPLIT * BB * E];

// ---------------------------------------------------------------------------
// K1: stream w/alpha/hebb once (192 MB). Each block: 64 rows x 512 cols.
// Depth-2 register software pipeline: while computing row k, rows k+1 and
// k+2's loads are in flight (9 LDG.128 outstanding per warp).
// ---------------------------------------------------------------------------
__global__ __launch_bounds__(128)
void k1_partial_gemm(const float* __restrict__ yin,
                     const float* __restrict__ hebb,
                     const float* __restrict__ w,
                     const float* __restrict__ alpha)
{
    const int cb  = blockIdx.x;            // 0..NCOLB-1
    const int rb  = blockIdx.y;            // 0..NSPLIT-1
    const int tid = threadIdx.x;           // 0..127
    const int j0  = cb * TJ + tid * 4;     // this thread's 4 columns
    const int k0  = rb * TK;

    // Stage yin[b, k0:k0+TK] in smem (broadcast reuse across 128 threads)
    __shared__ float yin_s[BB][TK];
    for (int i = tid; i < BB * TK; i += 128) {
        int b = i / TK, k = i % TK;
        yin_s[b][k] = yin[(size_t)b * E + k0 + k];
    }
    __syncthreads();

    float acc[BB][4];
#pragma unroll
    for (int b = 0; b < BB; b++) {
        acc[b][0] = 0.f; acc[b][1] = 0.f; acc[b][2] = 0.f; acc[b][3] = 0.f;
    }

    const size_t base0 = (size_t)k0 * E + j0;
    const float4* wp = (const float4*)(w     + base0);
    const float4* ap = (const float4*)(alpha + base0);
    const float4* hp = (const float4*)(hebb  + base0);
    const int strideV = E / 4;             // float4 row stride

    // Prime the pipeline: rows 0 and 1 in flight
    float4 w0 = __ldcs(wp);
    float4 a0 = __ldcs(ap);
    float4 h0 = __ldg (hp);
    float4 w1 = __ldcs(wp + strideV);
    float4 a1 = __ldcs(ap + strideV);
    float4 h1 = __ldg (hp + strideV);

#pragma unroll 8
    for (int k = 0; k < TK; k++) {
        float4 wn, an, hn;
        if (k + 2 < TK) {
            const int off = (k + 2) * strideV;
            wn = __ldcs(wp + off);
            an = __ldcs(ap + off);
            hn = __ldg (hp + off);
        }

        float4 m;
        m.x = fmaf(a0.x, h0.x, w0.x);
        m.y = fmaf(a0.y, h0.y, w0.y);
        m.z = fmaf(a0.z, h0.z, w0.z);
        m.w = fmaf(a0.w, h0.w, w0.w);
#pragma unroll
        for (int b = 0; b < BB; b++) {
            const float yv = yin_s[b][k];
            acc[b][0] = fmaf(yv, m.x, acc[b][0]);
            acc[b][1] = fmaf(yv, m.y, acc[b][1]);
            acc[b][2] = fmaf(yv, m.z, acc[b][2]);
            acc[b][3] = fmaf(yv, m.w, acc[b][3]);
        }

        w0 = w1; a0 = a1; h0 = h1;
        w1 = wn; a1 = an; h1 = hn;
    }

#pragma unroll
    for (int b = 0; b < BB; b++) {
        float4 v = make_float4(acc[b][0], acc[b][1], acc[b][2], acc[b][3]);
        *(float4*)(g_scratch + ((size_t)rb * BB + b) * E + j0) = v;
    }
}

// ---------------------------------------------------------------------------
// K2: reduce splits + input, tanh -> yout (written to d_out[0 : BB*E])
// ---------------------------------------------------------------------------
__global__ __launch_bounds__(256)
void k2_yout(const float* __restrict__ input, float* __restrict__ yout)
{
    const int idx = blockIdx.x * 256 + threadIdx.x;  // 0 .. BB*E-1
    if (idx >= BB * E) return;
    float s = input[idx];
#pragma unroll
    for (int r = 0; r < NSPLIT; r++)
        s += g_scratch[(size_t)r * BB * E + idx];
    yout[idx] = tanhf(s);
}

// ---------------------------------------------------------------------------
// K3: hebb_new = (1-eta)*hebb + eta * yin0 (outer) yout0   (128 MB stream)
// ---------------------------------------------------------------------------
__global__ __launch_bounds__(256)
void k3_hebb(const float* __restrict__ hebb,
             const float* __restrict__ yin,    // row 0 used
             const float* __restrict__ eta,    // scalar
             const float* __restrict__ yout0,  // d_out row 0 (E floats)
             float* __restrict__ hebb_out)
{
    const float et    = eta[0];
    const float one_m = 1.0f - et;

    const int t = blockIdx.x * 256 + threadIdx.x;     // one float4 per thread
    const int n4 = (E * E) / 4;
    if (t >= n4) return;

    const int row = t / (E / 4);
    const int c4  = t % (E / 4);
    const float s = et * yin[row];                    // eta * yin0[row]

    const float4 h = *(const float4*)(hebb  + (size_t)t * 4);
    const float4 y = *(const float4*)(yout0 + (size_t)c4 * 4);
    float4 o;
    o.x = fmaf(one_m, h.x, s * y.x);
    o.y = fmaf(one_m, h.y, s * y.y);
    o.z = fmaf(one_m, h.z, s * y.z);
    o.w = fmaf(one_m, h.w, s * y.w);
    *(float4*)(hebb_out + (size_t)t * 4) = o;
}

// ---------------------------------------------------------------------------
// Launch: inputs in metadata order: input, yin, hebb, w, alpha, eta
// Output: [yout (8*4096) | hebb_new (4096*4096)] fp32
// ---------------------------------------------------------------------------
extern "C" void kernel_launch(void* const* d_in, const int* in_sizes, int n_in,
                              void* d_out, int out_size)
{
    const float* input = (const float*)d_in[0];
    const float* yin   = (const float*)d_in[1];
    const float* hebb  = (const float*)d_in[2];
    const float* w     = (const float*)d_in[3];
    const float* alpha = (const float*)d_in[4];
    const float* eta   = (const float*)d_in[5];

    float* out      = (float*)d_out;
    float* yout     = out;            // BB*E
    float* hebb_out = out + BB * E;   // E*E

    // K1: 8 col-blocks x 64 row-splits = 512 blocks (one full reg-limited wave)
    dim3 g1(NCOLB, NSPLIT);
    k1_partial_gemm<<<g1, 128>>>(yin, hebb, w, alpha);

    // K2: 32768 elems
    k2_yout<<<(BB * E + 255) / 256, 256>>>(input, yout);

    // K3: E*E/4 float4 threads
    const int n4 = (E * E) / 4;
    k3_hebb<<<(n4 + 255) / 256, 256>>>(hebb, yin, eta, yout, hebb_out);
}

// round 5
// speedup vs baseline: 1.1754x; 1.1045x over previous
#include <cuda_runtime.h>
#include <math.h>

// Problem constants
#define E   4096
#define BB  8          // batch
#define TJ  512        // columns per block in K1 (256 threads * float2)
#define TK  64         // rows per split in K1
#define NSPLIT (E / TK)   // 64 row-splits
#define NCOLB  (E / TJ)   // 8 column blocks

// Deterministic split-K scratch: [NSPLIT][BB][E] fp32 = 8 MB
__device__ float g_scratch[(size_t)NSPLIT * BB * E];

// ---------------------------------------------------------------------------
// K1: stream w/alpha/hebb once (192 MB). Each block: 64 rows x 512 cols.
// 2 cols/thread (float2) -> 16 acc regs -> ~55 regs -> 4 blocks/SM (50% occ).
// ---------------------------------------------------------------------------
__global__ __launch_bounds__(256, 4)
void k1_partial_gemm(const float* __restrict__ yin,
                     const float* __restrict__ hebb,
                     const float* __restrict__ w,
                     const float* __restrict__ alpha)
{
    const int cb  = blockIdx.x;            // 0..NCOLB-1
    const int rb  = blockIdx.y;            // 0..NSPLIT-1
    const int tid = threadIdx.x;           // 0..255
    const int j0  = cb * TJ + tid * 2;     // this thread's 2 columns
    const int k0  = rb * TK;

    // Stage yin[b, k0:k0+TK] in smem (broadcast reuse across 256 threads)
    __shared__ float yin_s[BB][TK];
    for (int i = tid; i < BB * TK; i += 256) {
        int b = i / TK, k = i % TK;
        yin_s[b][k] = yin[(size_t)b * E + k0 + k];
    }
    __syncthreads();

    float accx[BB], accy[BB];
#pragma unroll
    for (int b = 0; b < BB; b++) { accx[b] = 0.f; accy[b] = 0.f; }

    const size_t base0 = (size_t)k0 * E + j0;
    const float2* wp = (const float2*)(w     + base0);
    const float2* ap = (const float2*)(alpha + base0);
    const float2* hp = (const float2*)(hebb  + base0);
    const int strideV = E / 2;             // float2 row stride

    // Depth-2 pipeline: rows k and k+1 in flight
    float2 w0 = __ldcs(wp);
    float2 a0 = __ldcs(ap);
    float2 h0 = __ldg (hp);
    float2 w1 = __ldcs(wp + strideV);
    float2 a1 = __ldcs(ap + strideV);
    float2 h1 = __ldg (hp + strideV);

#pragma unroll 8
    for (int k = 0; k < TK; k++) {
        float2 wn, an, hn;
        if (k + 2 < TK) {
            const int off = (k + 2) * strideV;
            wn = __ldcs(wp + off);
            an = __ldcs(ap + off);
            hn = __ldg (hp + off);
        }

        const float mx = fmaf(a0.x, h0.x, w0.x);
        const float my = fmaf(a0.y, h0.y, w0.y);
#pragma unroll
        for (int b = 0; b < BB; b++) {
            const float yv = yin_s[b][k];
            accx[b] = fmaf(yv, mx, accx[b]);
            accy[b] = fmaf(yv, my, accy[b]);
        }

        w0 = w1; a0 = a1; h0 = h1;
        w1 = wn; a1 = an; h1 = hn;
    }

#pragma unroll
    for (int b = 0; b < BB; b++) {
        float2 v = make_float2(accx[b], accy[b]);
        *(float2*)(g_scratch + ((size_t)rb * BB + b) * E + j0) = v;
    }
}

// ---------------------------------------------------------------------------
// K2: reduce splits + input, tanh -> yout (written to d_out[0 : BB*E])
// ---------------------------------------------------------------------------
__global__ __launch_bounds__(256)
void k2_yout(const float* __restrict__ input, float* __restrict__ yout)
{
    const int idx = blockIdx.x * 256 + threadIdx.x;  // 0 .. BB*E-1
    if (idx >= BB * E) return;
    float s = input[idx];
#pragma unroll
    for (int r = 0; r < NSPLIT; r++)
        s += g_scratch[(size_t)r * BB * E + idx];
    yout[idx] = tanhf(s);
}

// ---------------------------------------------------------------------------
// K3: hebb_new = (1-eta)*hebb + eta * yin0 (outer) yout0   (128 MB stream)
// ---------------------------------------------------------------------------
__global__ __launch_bounds__(256)
void k3_hebb(const float* __restrict__ hebb,
             const float* __restrict__ yin,    // row 0 used
             const float* __restrict__ eta,    // scalar
             const float* __restrict__ yout0,  // d_out row 0 (E floats)
             float* __restrict__ hebb_out)
{
    const float et    = eta[0];
    const float one_m = 1.0f - et;

    const int t = blockIdx.x * 256 + threadIdx.x;     // one float4 per thread
    const int n4 = (E * E) / 4;
    if (t >= n4) return;

    const int row = t / (E / 4);
    const int c4  = t % (E / 4);
    const float s = et * yin[row];                    // eta * yin0[row]

    const float4 h = __ldcs((const float4*)(hebb + (size_t)t * 4));
    const float4 y = *(const float4*)(yout0 + (size_t)c4 * 4);
    float4 o;
    o.x = fmaf(one_m, h.x, s * y.x);
    o.y = fmaf(one_m, h.y, s * y.y);
    o.z = fmaf(one_m, h.z, s * y.z);
    o.w = fmaf(one_m, h.w, s * y.w);
    __stcs((float4*)(hebb_out + (size_t)t * 4), o);
}

// ---------------------------------------------------------------------------
// Launch: inputs in metadata order: input, yin, hebb, w, alpha, eta
// Output: [yout (8*4096) | hebb_new (4096*4096)] fp32
// ---------------------------------------------------------------------------
extern "C" void kernel_launch(void* const* d_in, const int* in_sizes, int n_in,
                              void* d_out, int out_size)
{
    const float* input = (const float*)d_in[0];
    const float* yin   = (const float*)d_in[1];
    const float* hebb  = (const float*)d_in[2];
    const float* w     = (const float*)d_in[3];
    const float* alpha = (const float*)d_in[4];
    const float* eta   = (const float*)d_in[5];

    float* out      = (float*)d_out;
    float* yout     = out;            // BB*E
    float* hebb_out = out + BB * E;   // E*E

    // K1: 8 col-blocks x 64 row-splits = 512 blocks x 256 threads
    dim3 g1(NCOLB, NSPLIT);
    k1_partial_gemm<<<g1, 256>>>(yin, hebb, w, alpha);

    // K2: 32768 elems
    k2_yout<<<(BB * E + 255) / 256, 256>>>(input, yout);

    // K3: E*E/4 float4 threads
    const int n4 = (E * E) / 4;
    k3_hebb<<<(n4 + 255) / 256, 256>>>(hebb, yin, eta, yout, hebb_out);
}